// round 13
// baseline (speedup 1.0000x reference)
#include <cuda_runtime.h>
#include <cuda_fp16.h>
#include <math.h>
#include <stdint.h>

// PatchEmbedding, fused im2col + single-pass fp16 mma.sync GEMM (sm_103 non-'a').
// D = GELU( A @ W + b ), M=12544 (64*196), K=768, N=768, fp32 in/out, fp32 accum.
//
// A path fused: LDG.128 fp32 image chunks (im2col addressing; every 16B chunk is
// contiguous+aligned in NHWC) -> cvt fp16 -> STS into double-buffered swizzled
// A smem tiles. B: fp16 [N,K] scratch via one transpose kernel, 3-stage cp.async
// with 2 groups in flight (refill targets stage (kt+2)%3, never the stage being
// read this iteration -- R12's refill-current-stage race is the fixed bug).
// CTA 128x128, 8 warps (4M x 2N), warp tile 32x64, BK=64, occupancy 2.

#define M_TOTAL 12544
#define K_TOTAL 768
#define N_TOTAL 768
#define BM      128
#define BN      128
#define BK      64              // fp16 k per tile (128 B rows, swizzled)
#define KTILES  12              // 768 / 64
#define TILE_B  16384           // 128 rows * 128 B (fp16 tile)
// smem layout: [A16_0][A16_1][B0][B1][B2]
#define OFF_A0  0
#define OFF_A1  TILE_B
#define OFF_B   (2 * TILE_B)
#define SMEM_DYN (5 * TILE_B + 1024)

// ---------------- device scratch ----------------
__device__ __half g_B16[(size_t)N_TOTAL * K_TOTAL];   // W transposed: [N,K]

__device__ __forceinline__ float gelu_exact(float x) {
    return 0.5f * x * (1.0f + erff(x * 0.70710678118654752f));
}
__device__ __forceinline__ uint32_t s2u(const void* p) {
    uint32_t a;
    asm("{ .reg .u64 t; cvta.to.shared.u64 t, %1; cvt.u32.u64 %0, t; }" : "=r"(a) : "l"(p));
    return a;
}

// ---------------- prep: W [K,N] -> [N,K] fp16 ----------------
__global__ __launch_bounds__(1024) void wprep(const float* __restrict__ W) {
    __shared__ float ts[32][33];
    int k0 = blockIdx.y * 32, n0 = blockIdx.x * 32;
    ts[threadIdx.y][threadIdx.x] =
        W[(size_t)(k0 + threadIdx.y) * N_TOTAL + n0 + threadIdx.x];
    __syncthreads();
    g_B16[(size_t)(n0 + threadIdx.y) * K_TOTAL + (k0 + threadIdx.x)] =
        __float2half_rn(ts[threadIdx.x][threadIdx.y]);
}

// ---------------- smem addressing ----------------
// fp16 tile row = 64 fp16 = 128 B = 8 x 16B chunks; swizzle: chunk ^= (row & 7)
__device__ __forceinline__ uint32_t sw_off(int row, int chunk) {
    return (uint32_t)(row * 128 + (((chunk) ^ (row & 7)) << 4));
}
__device__ __forceinline__ void cpa16(uint32_t dst, const void* src) {
    asm volatile("cp.async.cg.shared.global [%0], [%1], 16;" ::"r"(dst), "l"(src)
                 : "memory");
}

// im2col: gmem float offset of patch-row start for GEMM row m (pi=0, k-rem=0)
__device__ __forceinline__ uint32_t row_gbase(int m) {
    int b = m / 196, np = m - b * 196;
    int ph = np / 14, pw = np - ph * 14;
    return (uint32_t)(((b * 224 + ph * 16) * 224 + pw * 16) * 3);
}
// float offset within a row of 4-float group jj (0..15) at k-tile kc
__device__ __forceinline__ uint32_t chunk_off(int kc, int jj) {
    int k4 = kc * 64 + jj * 4;
    int pi = k4 / 48;
    return (uint32_t)(pi * 672 + (k4 - pi * 48));   // 672 = 224*3
}

// B tile loader: 1024 16B chunks / 256 threads
__device__ __forceinline__ void load_B(uint32_t st, int kt, int nBlock, int tid) {
    const __half* gB = g_B16 + (size_t)nBlock * K_TOTAL + (size_t)kt * BK;
#pragma unroll
    for (int i = 0; i < 4; ++i) {
        int cid = i * 256 + tid;
        int row = cid >> 3, ch = cid & 7;
        cpa16(st + sw_off(row, ch), gB + (size_t)row * K_TOTAL + ch * 8);
    }
}

#define LDSM_X4(r0, r1, r2, r3, addr)                                            \
    asm volatile("ldmatrix.sync.aligned.m8n8.x4.shared.b16 {%0,%1,%2,%3}, [%4];" \
                 : "=r"(r0), "=r"(r1), "=r"(r2), "=r"(r3) : "r"(addr))

#define MMA16816(c, a0, a1, a2, a3, b0, b1)                                     \
    asm volatile("mma.sync.aligned.m16n8k16.row.col.f32.f16.f16.f32 "           \
                 "{%0,%1,%2,%3}, {%4,%5,%6,%7}, {%8,%9}, {%0,%1,%2,%3};"        \
                 : "+f"((c)[0]), "+f"((c)[1]), "+f"((c)[2]), "+f"((c)[3])       \
                 : "r"(a0), "r"(a1), "r"(a2), "r"(a3), "r"(b0), "r"(b1))

#define CP_WAIT(n) asm volatile("cp.async.wait_group %0;" ::"n"(n) : "memory")
#define CP_COMMIT() asm volatile("cp.async.commit_group;" ::: "memory")

// ---------------- main fused kernel ----------------
__global__ __launch_bounds__(256, 2) void patch_gemm(const float* __restrict__ img,
                                                     const float* __restrict__ bias,
                                                     float* __restrict__ out) {
    extern __shared__ char dyn[];
    __shared__ float bias_s[BN];

    const int tid = threadIdx.x;
    const int wid = tid >> 5, lane = tid & 31;
    const int wm = wid & 3;          // 4 warps in M: 32 rows each
    const int wn = wid >> 2;         // 2 warps in N: 64 cols each
    const int nBlock = blockIdx.x * BN;
    const int mBlock = blockIdx.y * BM;

    const uint32_t sbase = (s2u(dyn) + 1023u) & ~1023u;
    char* const sgen = dyn + (sbase - s2u(dyn));   // generic ptr matching sbase

    if (tid < BN) bias_s[tid] = bias[nBlock + tid];

    // ---- fused-A addressing: thread handles rows r0+{0,32,64,96}, groups {j, j+8}
    const int r0 = tid >> 3;
    const int j = tid & 7;
    uint32_t abase[4];
#pragma unroll
    for (int i = 0; i < 4; ++i) abase[i] = row_gbase(mBlock + r0 + i * 32);

    // byte offsets within an A tile for this thread's two 4-half groups, per row i
    uint32_t ad0[4], ad1[4];
#pragma unroll
    for (int i = 0; i < 4; ++i) {
        int r = r0 + i * 32;
        ad0[i] = (uint32_t)(r * 128 + (((j >> 1) ^ (r & 7)) << 4) + (j & 1) * 8);
        ad1[i] = (uint32_t)(r * 128 + ((((j + 8) >> 1) ^ (r & 7)) << 4) + ((j + 8) & 1) * 8);
    }

    // ldmatrix per-lane addressing
    const int lr = (lane & 7) + ((lane >> 3) & 1) * 8;  // row-in-16-block, 0..15
    const int lco = lane >> 4;                          // 0/1: +16B chunk

    float acc[2][8][4];
#pragma unroll
    for (int mi = 0; mi < 2; ++mi)
#pragma unroll
        for (int nj = 0; nj < 8; ++nj)
#pragma unroll
            for (int r = 0; r < 4; ++r) acc[mi][nj][r] = 0.0f;

    // ---- prologue ----
    // B: stages 0,1 (2 groups in flight, R11-proven schedule)
    load_B(sbase + OFF_B + 0 * TILE_B, 0, nBlock, tid); CP_COMMIT();
    load_B(sbase + OFF_B + 1 * TILE_B, 1, nBlock, tid); CP_COMMIT();
    // A: tile 0 -> A16[0] (LDG -> cvt -> STS)
    {
        uint32_t o0 = chunk_off(0, j), o1 = chunk_off(0, j + 8);
#pragma unroll
        for (int i = 0; i < 4; ++i) {
            float4 f0 = *(const float4*)(img + abase[i] + o0);
            float4 f1 = *(const float4*)(img + abase[i] + o1);
            char* base = sgen + OFF_A0;
            *(__half2*)(base + ad0[i])     = __floats2half2_rn(f0.x, f0.y);
            *(__half2*)(base + ad0[i] + 4) = __floats2half2_rn(f0.z, f0.w);
            *(__half2*)(base + ad1[i])     = __floats2half2_rn(f1.x, f1.y);
            *(__half2*)(base + ad1[i] + 4) = __floats2half2_rn(f1.z, f1.w);
        }
    }

#pragma unroll 1
    for (int kt = 0; kt < KTILES; ++kt) {
        const int kn = kt + 1;
        const bool haveNext = (kn < KTILES);
        uint32_t o0 = 0, o1 = 0;
        float4 fa[2], fb[2];            // two row-pairs staged at a time
        if (haveNext) {
            o0 = chunk_off(kn, j);
            o1 = chunk_off(kn, j + 8);
            fa[0] = *(const float4*)(img + abase[0] + o0);
            fb[0] = *(const float4*)(img + abase[0] + o1);
            fa[1] = *(const float4*)(img + abase[1] + o0);
            fb[1] = *(const float4*)(img + abase[1] + o1);
        }

        if (kt + 1 < KTILES) CP_WAIT(1);
        else                 CP_WAIT(0);
        __syncthreads();

        const uint32_t aS = sbase + ((kt & 1) ? OFF_A1 : OFF_A0);
        const uint32_t bS = sbase + OFF_B + (kt % 3) * TILE_B;
        char* const aNg = sgen + ((kn & 1) ? OFF_A1 : OFF_A0);

#pragma unroll
        for (int ks = 0; ks < 4; ++ks) {
            const int c0 = 2 * ks + lco;
            uint32_t a[2][4];
#pragma unroll
            for (int mi = 0; mi < 2; ++mi) {
                int r = wm * 32 + mi * 16 + lr;
                LDSM_X4(a[mi][0], a[mi][1], a[mi][2], a[mi][3], aS + sw_off(r, c0));
            }
            uint32_t b[4][4];
#pragma unroll
            for (int g = 0; g < 4; ++g) {
                int r = wn * 64 + g * 16 + lr;
                LDSM_X4(b[g][0], b[g][1], b[g][2], b[g][3], bS + sw_off(r, c0));
            }
#pragma unroll
            for (int mi = 0; mi < 2; ++mi)
#pragma unroll
                for (int g = 0; g < 4; ++g) {
                    MMA16816(acc[mi][2 * g], a[mi][0], a[mi][1], a[mi][2], a[mi][3],
                             b[g][0], b[g][2]);
                    MMA16816(acc[mi][2 * g + 1], a[mi][0], a[mi][1], a[mi][2], a[mi][3],
                             b[g][1], b[g][3]);
                }

            // after ks==1: flush staged rows 0,1 of next A tile; load rows 2,3
            if (ks == 1 && haveNext) {
#pragma unroll
                for (int i = 0; i < 2; ++i) {
                    *(__half2*)(aNg + ad0[i])     = __floats2half2_rn(fa[i].x, fa[i].y);
                    *(__half2*)(aNg + ad0[i] + 4) = __floats2half2_rn(fa[i].z, fa[i].w);
                    *(__half2*)(aNg + ad1[i])     = __floats2half2_rn(fb[i].x, fb[i].y);
                    *(__half2*)(aNg + ad1[i] + 4) = __floats2half2_rn(fb[i].z, fb[i].w);
                }
                fa[0] = *(const float4*)(img + abase[2] + o0);
                fb[0] = *(const float4*)(img + abase[2] + o1);
                fa[1] = *(const float4*)(img + abase[3] + o0);
                fb[1] = *(const float4*)(img + abase[3] + o1);
            }
            // after ks==3: flush rows 2,3
            if (ks == 3 && haveNext) {
#pragma unroll
                for (int i = 0; i < 2; ++i) {
                    *(__half2*)(aNg + ad0[i + 2])     = __floats2half2_rn(fa[i].x, fa[i].y);
                    *(__half2*)(aNg + ad0[i + 2] + 4) = __floats2half2_rn(fa[i].z, fa[i].w);
                    *(__half2*)(aNg + ad1[i + 2])     = __floats2half2_rn(fb[i].x, fb[i].y);
                    *(__half2*)(aNg + ad1[i + 2] + 4) = __floats2half2_rn(fb[i].z, fb[i].w);
                }
            }
        }

        // refill B stage (kt+2)%3 with tile kt+2 -- never the stage read this iter
        if (kt + 2 < KTILES) {
            load_B(sbase + OFF_B + ((kt + 2) % 3) * TILE_B, kt + 2, nBlock, tid);
            CP_COMMIT();
        }
    }

    // ---------------- epilogue: bias + exact GELU ----------------
    const int tig = lane & 3, gid = lane >> 2;
#pragma unroll
    for (int mi = 0; mi < 2; ++mi) {
        const int row0 = mBlock + wm * 32 + mi * 16 + gid;
#pragma unroll
        for (int nj = 0; nj < 8; ++nj) {
            const int cloc = wn * 64 + nj * 8 + tig * 2;
            const float b0 = bias_s[cloc], b1 = bias_s[cloc + 1];
            float2 v0, v1;
            v0.x = gelu_exact(acc[mi][nj][0] + b0);
            v0.y = gelu_exact(acc[mi][nj][1] + b1);
            v1.x = gelu_exact(acc[mi][nj][2] + b0);
            v1.y = gelu_exact(acc[mi][nj][3] + b1);
            *(float2*)(out + (size_t)row0 * N_TOTAL + nBlock + cloc) = v0;
            *(float2*)(out + (size_t)(row0 + 8) * N_TOTAL + nBlock + cloc) = v1;
        }
    }
}

// ---------------- launch ----------------
extern "C" void kernel_launch(void* const* d_in, const int* in_sizes, int n_in,
                              void* d_out, int out_size) {
    const float* img = (const float*)d_in[0];   // [64,224,224,3]
    const float* Wp = (const float*)d_in[1];    // [768,768]
    const float* bias = (const float*)d_in[2];  // [768]
    float* out = (float*)d_out;                 // [64,196,768]

    cudaFuncSetAttribute(patch_gemm, cudaFuncAttributeMaxDynamicSharedMemorySize,
                         SMEM_DYN);

    wprep<<<dim3(N_TOTAL / 32, K_TOTAL / 32), dim3(32, 32)>>>(Wp);
    patch_gemm<<<dim3(N_TOTAL / BN, M_TOTAL / BM), 256, SMEM_DYN>>>(img, bias, out);
}

// round 14
// speedup vs baseline: 1.0495x; 1.0495x over previous
#include <cuda_runtime.h>
#include <cuda_fp16.h>
#include <math.h>
#include <stdint.h>

// PatchEmbedding: warp-specialized fused im2col + fp16 mma.sync GEMM (sm_103).
// D = GELU( A @ W + b ), M=12544 (64*196), K=768, N=768, fp32 in/out, fp32 accum.
//
// 320 threads/CTA: warps 0-7 = compute (pure LDSM+HMMA mainloop, R11 layout:
// 4M x 2N warps, 32x64 warp tile), warps 8-9 = producers (A: LDG.128 fp32 image
// chunks via im2col addressing -> cvt fp16 -> STS.128 into swizzled double-
// buffered A tiles; B: cp.async from fp16 [N,K] scratch, 3-stage).
// Producers write A[(kt+1)&1], B[(kt+2)%3] while compute reads A[kt&1], B[kt%3].

#define M_TOTAL 12544
#define K_TOTAL 768
#define N_TOTAL 768
#define BM      128
#define BN      128
#define KTILES  12              // 768 / 64
#define TILE_B  16384           // 128 rows * 128 B (fp16 tile)
#define OFF_A0  0
#define OFF_A1  TILE_B
#define OFF_B   (2 * TILE_B)
#define SMEM_DYN (5 * TILE_B + 1024)
#define NTH     320
#define NCOMP   256

// ---------------- device scratch ----------------
__device__ __half g_B16[(size_t)N_TOTAL * K_TOTAL];   // W transposed: [N,K]

__device__ __forceinline__ float gelu_exact(float x) {
    return 0.5f * x * (1.0f + erff(x * 0.70710678118654752f));
}
__device__ __forceinline__ uint32_t s2u(const void* p) {
    uint32_t a;
    asm("{ .reg .u64 t; cvta.to.shared.u64 t, %1; cvt.u32.u64 %0, t; }" : "=r"(a) : "l"(p));
    return a;
}
__device__ __forceinline__ uint32_t f2h2(float a, float b) {
    __half2 h = __floats2half2_rn(a, b);
    return *(uint32_t*)&h;
}

// ---------------- prep: W [K,N] -> [N,K] fp16 ----------------
__global__ __launch_bounds__(1024) void wprep(const float* __restrict__ W) {
    __shared__ float ts[32][33];
    int k0 = blockIdx.y * 32, n0 = blockIdx.x * 32;
    ts[threadIdx.y][threadIdx.x] =
        W[(size_t)(k0 + threadIdx.y) * N_TOTAL + n0 + threadIdx.x];
    __syncthreads();
    g_B16[(size_t)(n0 + threadIdx.y) * K_TOTAL + (k0 + threadIdx.x)] =
        __float2half_rn(ts[threadIdx.x][threadIdx.y]);
}

// ---------------- addressing helpers ----------------
// fp16 tile row = 64 fp16 = 128 B = 8 x 16B chunks; swizzle: chunk ^= (row & 7)
__device__ __forceinline__ uint32_t sw_off(int row, int chunk) {
    return (uint32_t)(row * 128 + (((chunk) ^ (row & 7)) << 4));
}
__device__ __forceinline__ void cpa16(uint32_t dst, const void* src) {
    asm volatile("cp.async.cg.shared.global [%0], [%1], 16;" ::"r"(dst), "l"(src)
                 : "memory");
}
// im2col: gmem float offset of patch-row start for GEMM row m (pi=0, k-rem=0)
__device__ __forceinline__ uint32_t row_gbase(int m) {
    int b = m / 196, np = m - b * 196;
    int ph = np / 14, pw = np - ph * 14;
    return (uint32_t)(((b * 224 + ph * 16) * 224 + pw * 16) * 3);
}
// float offset within a row for 4-float group jj (0..15) at k-tile kc
__device__ __forceinline__ uint32_t chunk_off(int kc, int jj) {
    int k4 = kc * 64 + jj * 4;
    int pi = k4 / 48;
    return (uint32_t)(pi * 672 + (k4 - pi * 48));   // 672 = 224*3
}

#define LDSM_X4(r0, r1, r2, r3, addr)                                            \
    asm volatile("ldmatrix.sync.aligned.m8n8.x4.shared.b16 {%0,%1,%2,%3}, [%4];" \
                 : "=r"(r0), "=r"(r1), "=r"(r2), "=r"(r3) : "r"(addr))

#define MMA16816(c, a0, a1, a2, a3, b0, b1)                                     \
    asm volatile("mma.sync.aligned.m16n8k16.row.col.f32.f16.f16.f32 "           \
                 "{%0,%1,%2,%3}, {%4,%5,%6,%7}, {%8,%9}, {%0,%1,%2,%3};"        \
                 : "+f"((c)[0]), "+f"((c)[1]), "+f"((c)[2]), "+f"((c)[3])       \
                 : "r"(a0), "r"(a1), "r"(a2), "r"(a3), "r"(b0), "r"(b1))

#define CP_WAIT(n) asm volatile("cp.async.wait_group %0;" ::"n"(n) : "memory")
#define CP_COMMIT() asm volatile("cp.async.commit_group;" ::: "memory")

// ---------------- producer helpers ----------------
// Load 4 chunks' worth of image data (8 float4) into buf.
// Chunk i covers rows rbase[i]; groups o0 (k..k+3), o1 (k+4..k+7).
__device__ __forceinline__ void ldA4(float4* buf, const float* img,
                                     const uint32_t* rbase, int i0,
                                     uint32_t o0, uint32_t o1) {
#pragma unroll
    for (int q = 0; q < 4; ++q) {
        buf[2 * q]     = *(const float4*)(img + rbase[i0 + q] + o0);
        buf[2 * q + 1] = *(const float4*)(img + rbase[i0 + q] + o1);
    }
}
// Convert + store 4 chunks (STS.128 each) at dstBase + (i0+q)*1024.
__device__ __forceinline__ void stA4(char* aDst, uint32_t dstBase, int i0,
                                     const float4* buf) {
#pragma unroll
    for (int q = 0; q < 4; ++q) {
        uint4 v;
        v.x = f2h2(buf[2 * q].x, buf[2 * q].y);
        v.y = f2h2(buf[2 * q].z, buf[2 * q].w);
        v.z = f2h2(buf[2 * q + 1].x, buf[2 * q + 1].y);
        v.w = f2h2(buf[2 * q + 1].z, buf[2 * q + 1].w);
        *(uint4*)(aDst + dstBase + (uint32_t)(i0 + q) * 1024) = v;
    }
}
// Stage one full A tile (this thread's 16 chunks), 2-deep pipelined.
__device__ __forceinline__ void stageA(const float* img, char* aDst,
                                       const uint32_t* rbase, uint32_t dstBase,
                                       int kt, int ch) {
    const uint32_t o0 = chunk_off(kt, 2 * ch);
    const uint32_t o1 = chunk_off(kt, 2 * ch + 1);
    float4 bufA[8], bufB[8];
    ldA4(bufA, img, rbase, 0, o0, o1);
    ldA4(bufB, img, rbase, 4, o0, o1);
    stA4(aDst, dstBase, 0, bufA);
    ldA4(bufA, img, rbase, 8, o0, o1);
    stA4(aDst, dstBase, 4, bufB);
    ldA4(bufB, img, rbase, 12, o0, o1);
    stA4(aDst, dstBase, 8, bufA);
    stA4(aDst, dstBase, 12, bufB);
}
// Issue B tile cp.async (this thread's 16 chunks).
__device__ __forceinline__ void issueB(uint32_t st, int kt, int nBlock,
                                       int r0p, int ch) {
    const char* src = (const char*)(g_B16 + (size_t)nBlock * K_TOTAL + (size_t)kt * 64)
                      + r0p * (K_TOTAL * 2) + ch * 16;
    uint32_t dst = st + (uint32_t)(r0p * 128 + ((ch ^ r0p) << 4));
#pragma unroll
    for (int i = 0; i < 16; ++i)
        cpa16(dst + (uint32_t)i * 1024, src + (size_t)i * 8 * (K_TOTAL * 2));
}

// ---------------- main fused kernel ----------------
__global__ __launch_bounds__(NTH, 2) void patch_gemm(const float* __restrict__ img,
                                                     const float* __restrict__ bias,
                                                     float* __restrict__ out) {
    extern __shared__ char dyn[];
    __shared__ float bias_s[BN];

    const int tid = threadIdx.x;
    const int nBlock = blockIdx.x * BN;
    const int mBlock = blockIdx.y * BM;

    const uint32_t sbase = (s2u(dyn) + 1023u) & ~1023u;
    char* const sgen = dyn + (sbase - s2u(dyn));   // generic ptr matching sbase

    if (tid < BN) bias_s[tid] = bias[nBlock + tid];

    if (tid >= NCOMP) {
        // ================= producer path (warps 8,9) =================
        const int ptid = tid - NCOMP;        // 0..63
        const int ch = ptid & 7;             // fixed 16B chunk column
        const int r0p = ptid >> 3;           // 0..7; rows r0p + 8i
        const uint32_t dstBase = (uint32_t)(r0p * 128 + ((ch ^ r0p) << 4));

        uint32_t rbase[16];
#pragma unroll
        for (int i = 0; i < 16; ++i) rbase[i] = row_gbase(mBlock + r0p + 8 * i);

        // prologue: B0, B1 async; A0 staged; B0 guaranteed arrived
        issueB(sbase + OFF_B + 0 * TILE_B, 0, nBlock, r0p, ch); CP_COMMIT();
        issueB(sbase + OFF_B + 1 * TILE_B, 1, nBlock, r0p, ch); CP_COMMIT();
        stageA(img, sgen + OFF_A0, rbase, dstBase, 0, ch);
        CP_WAIT(1);

#pragma unroll 1
        for (int kt = 0; kt < KTILES; ++kt) {
            __syncthreads();   // compute may now read A[kt&1], B[kt%3]
            if (kt + 1 < KTILES)
                stageA(img, sgen + ((kt + 1) & 1 ? OFF_A1 : OFF_A0), rbase,
                       dstBase, kt + 1, ch);
            if (kt + 2 < KTILES) {
                issueB(sbase + OFF_B + ((kt + 2) % 3) * TILE_B, kt + 2, nBlock,
                       r0p, ch);
                CP_COMMIT();
                CP_WAIT(1);    // B[kt+1] complete before next barrier
            } else if (kt + 1 < KTILES) {
                CP_WAIT(0);    // last tile's B must be complete
            }
        }
    } else {
        // ================= compute path (warps 0-7) =================
        const int wid = tid >> 5, lane = tid & 31;
        const int wm = wid & 3;          // 4 warps in M: 32 rows each
        const int wn = wid >> 2;         // 2 warps in N: 64 cols each
        const int lr = (lane & 7) + ((lane >> 3) & 1) * 8;  // 0..15
        const int lco = lane >> 4;                          // 0/1

        float acc[2][8][4];
#pragma unroll
        for (int mi = 0; mi < 2; ++mi)
#pragma unroll
            for (int nj = 0; nj < 8; ++nj)
#pragma unroll
                for (int r = 0; r < 4; ++r) acc[mi][nj][r] = 0.0f;

#pragma unroll 1
        for (int kt = 0; kt < KTILES; ++kt) {
            __syncthreads();
            const uint32_t aS = sbase + ((kt & 1) ? OFF_A1 : OFF_A0);
            const uint32_t bS = sbase + OFF_B + (kt % 3) * TILE_B;

#pragma unroll
            for (int ks = 0; ks < 4; ++ks) {
                const int c0 = 2 * ks + lco;
                uint32_t a[2][4];
#pragma unroll
                for (int mi = 0; mi < 2; ++mi) {
                    int r = wm * 32 + mi * 16 + lr;
                    LDSM_X4(a[mi][0], a[mi][1], a[mi][2], a[mi][3],
                            aS + sw_off(r, c0));
                }
                uint32_t b[2][4];
#pragma unroll
                for (int g = 0; g < 2; ++g) {
                    int r = wn * 64 + g * 16 + lr;
                    LDSM_X4(b[g][0], b[g][1], b[g][2], b[g][3], bS + sw_off(r, c0));
                }
#pragma unroll
                for (int mi = 0; mi < 2; ++mi)
#pragma unroll
                    for (int g = 0; g < 2; ++g) {
                        MMA16816(acc[mi][2 * g], a[mi][0], a[mi][1], a[mi][2],
                                 a[mi][3], b[g][0], b[g][2]);
                        MMA16816(acc[mi][2 * g + 1], a[mi][0], a[mi][1], a[mi][2],
                                 a[mi][3], b[g][1], b[g][3]);
                    }
#pragma unroll
                for (int g = 0; g < 2; ++g) {
                    int r = wn * 64 + (g + 2) * 16 + lr;
                    LDSM_X4(b[g][0], b[g][1], b[g][2], b[g][3], bS + sw_off(r, c0));
                }
#pragma unroll
                for (int mi = 0; mi < 2; ++mi)
#pragma unroll
                    for (int g = 0; g < 2; ++g) {
                        MMA16816(acc[mi][2 * (g + 2)], a[mi][0], a[mi][1], a[mi][2],
                                 a[mi][3], b[g][0], b[g][2]);
                        MMA16816(acc[mi][2 * (g + 2) + 1], a[mi][0], a[mi][1],
                                 a[mi][2], a[mi][3], b[g][1], b[g][3]);
                    }
            }
        }

        // ---------------- epilogue: bias + exact GELU ----------------
        const int tig = lane & 3, gid = lane >> 2;
#pragma unroll
        for (int mi = 0; mi < 2; ++mi) {
            const int row0 = mBlock + wm * 32 + mi * 16 + gid;
#pragma unroll
            for (int nj = 0; nj < 8; ++nj) {
                const int cloc = wn * 64 + nj * 8 + tig * 2;
                const float b0 = bias_s[cloc], b1 = bias_s[cloc + 1];
                float2 v0, v1;
                v0.x = gelu_exact(acc[mi][nj][0] + b0);
                v0.y = gelu_exact(acc[mi][nj][1] + b1);
                v1.x = gelu_exact(acc[mi][nj][2] + b0);
                v1.y = gelu_exact(acc[mi][nj][3] + b1);
                *(float2*)(out + (size_t)row0 * N_TOTAL + nBlock + cloc) = v0;
                *(float2*)(out + (size_t)(row0 + 8) * N_TOTAL + nBlock + cloc) = v1;
            }
        }
    }
}

// ---------------- launch ----------------
extern "C" void kernel_launch(void* const* d_in, const int* in_sizes, int n_in,
                              void* d_out, int out_size) {
    const float* img = (const float*)d_in[0];   // [64,224,224,3]
    const float* Wp = (const float*)d_in[1];    // [768,768]
    const float* bias = (const float*)d_in[2];  // [768]
    float* out = (float*)d_out;                 // [64,196,768]

    cudaFuncSetAttribute(patch_gemm, cudaFuncAttributeMaxDynamicSharedMemorySize,
                         SMEM_DYN);

    wprep<<<dim3(N_TOTAL / 32, K_TOTAL / 32), dim3(32, 32)>>>(Wp);
    patch_gemm<<<dim3(N_TOTAL / BN, M_TOTAL / BM), NTH, SMEM_DYN>>>(img, bias, out);
}

// round 15
// speedup vs baseline: 1.1192x; 1.0664x over previous
#include <cuda_runtime.h>
#include <cuda_fp16.h>
#include <math.h>
#include <stdint.h>

// PatchEmbedding via single-pass fp16 mma.sync GEMM (sm_103 non-'a': no tcgen05).
// D = GELU( A @ W + b ), M=12544, K=768, N=768, fp32 in/out, fp32 accumulate.
//
// R11 architecture (prep im2col -> fp16 scratch; GEMM all-cp.async, 3-stage,
// CTA 128x128, 8 warps 4Mx2N, warp tile 32x64, occ 2) + register-level
// double buffering of ldmatrix fragments: LDSM for k-step ks+1 issues while
// MMAs for ks execute, removing the per-ks dependent LDSM->MMA stall.

#define M_TOTAL 12544
#define K_TOTAL 768
#define N_TOTAL 768
#define BM      128
#define BN      128
#define BK      64              // fp16 per k-tile row chunk (128 B rows)
#define KTILES  12              // 768 / 64
#define TILE_B  16384           // 128 rows * 128 B
#define STAGE_B (2 * TILE_B)    // A tile + B tile
#define NSTAGE  3
#define SMEM_DYN (NSTAGE * STAGE_B + 1024)

// ---------------- device scratch ----------------
__device__ __half g_A16[(size_t)M_TOTAL * K_TOTAL];
__device__ __half g_B16[(size_t)N_TOTAL * K_TOTAL];   // W transposed: [N,K]

__device__ __forceinline__ float gelu_exact(float x) {
    return 0.5f * x * (1.0f + erff(x * 0.70710678118654752f));
}
__device__ __forceinline__ uint32_t s2u(const void* p) {
    uint32_t a;
    asm("{ .reg .u64 t; cvta.to.shared.u64 t, %1; cvt.u32.u64 %0, t; }" : "=r"(a) : "l"(p));
    return a;
}

// ---------------- prep 1: im2col + fp16 convert (16 elems/thread) ----------------
__global__ __launch_bounds__(256) void im2col_prep(const float* __restrict__ img) {
    int t = blockIdx.x * 256 + threadIdx.x;       // M*K/16 threads
    int e = t << 4;
    int m = e / K_TOTAL;
    int k = e - m * K_TOTAL;
    int pi = k / 48, rem = k - pi * 48;           // 16-groups never cross 48-boundary
    int b = m / 196, np = m - b * 196;
    int ph = np / 14, pw = np - ph * 14;
    const float* src =
        img + (size_t)(((b * 224 + ph * 16 + pi) * 224 + pw * 16) * 3 + rem);
    float4 v0 = *(const float4*)src;
    float4 v1 = *(const float4*)(src + 4);
    float4 v2 = *(const float4*)(src + 8);
    float4 v3 = *(const float4*)(src + 12);

    union { __half h[16]; uint4 u[2]; } o;
    o.h[0]  = __float2half_rn(v0.x); o.h[1]  = __float2half_rn(v0.y);
    o.h[2]  = __float2half_rn(v0.z); o.h[3]  = __float2half_rn(v0.w);
    o.h[4]  = __float2half_rn(v1.x); o.h[5]  = __float2half_rn(v1.y);
    o.h[6]  = __float2half_rn(v1.z); o.h[7]  = __float2half_rn(v1.w);
    o.h[8]  = __float2half_rn(v2.x); o.h[9]  = __float2half_rn(v2.y);
    o.h[10] = __float2half_rn(v2.z); o.h[11] = __float2half_rn(v2.w);
    o.h[12] = __float2half_rn(v3.x); o.h[13] = __float2half_rn(v3.y);
    o.h[14] = __float2half_rn(v3.z); o.h[15] = __float2half_rn(v3.w);
    uint4* dst = (uint4*)(g_A16 + (size_t)m * K_TOTAL + k);
    dst[0] = o.u[0];
    dst[1] = o.u[1];
}

// ---------------- prep 2: W [K,N] -> [N,K] fp16 ----------------
__global__ __launch_bounds__(1024) void wprep(const float* __restrict__ W) {
    __shared__ float ts[32][33];
    int k0 = blockIdx.y * 32, n0 = blockIdx.x * 32;
    ts[threadIdx.y][threadIdx.x] =
        W[(size_t)(k0 + threadIdx.y) * N_TOTAL + n0 + threadIdx.x];
    __syncthreads();
    g_B16[(size_t)(n0 + threadIdx.y) * K_TOTAL + (k0 + threadIdx.x)] =
        __float2half_rn(ts[threadIdx.x][threadIdx.y]);
}

// ---------------- smem helpers ----------------
// tile row = 64 fp16 = 128 B = 8 x 16B chunks; swizzle: chunk ^= (row & 7)
__device__ __forceinline__ uint32_t sw_off(int row, int chunk) {
    return (uint32_t)(row * 128 + (((chunk) ^ (row & 7)) << 4));
}
__device__ __forceinline__ void cpa16(uint32_t dst, const void* src) {
    asm volatile("cp.async.cg.shared.global [%0], [%1], 16;" ::"r"(dst), "l"(src)
                 : "memory");
}

__device__ __forceinline__ void load_stage(uint32_t st, int kt, int mBlock, int nBlock,
                                           int tid) {
    const size_t kOff = (size_t)kt * BK;
    const __half* gA = g_A16 + (size_t)mBlock * K_TOTAL + kOff;
    const __half* gB = g_B16 + (size_t)nBlock * K_TOTAL + kOff;
#pragma unroll
    for (int i = 0; i < 4; ++i) {                 // A: 1024 chunks / 256 threads
        int cid = i * 256 + tid;
        int row = cid >> 3, ch = cid & 7;
        cpa16(st + sw_off(row, ch), gA + (size_t)row * K_TOTAL + ch * 8);
    }
#pragma unroll
    for (int i = 0; i < 4; ++i) {                 // B
        int cid = i * 256 + tid;
        int row = cid >> 3, ch = cid & 7;
        cpa16(st + TILE_B + sw_off(row, ch), gB + (size_t)row * K_TOTAL + ch * 8);
    }
}

#define LDSM_X4(r0, r1, r2, r3, addr)                                            \
    asm volatile("ldmatrix.sync.aligned.m8n8.x4.shared.b16 {%0,%1,%2,%3}, [%4];" \
                 : "=r"(r0), "=r"(r1), "=r"(r2), "=r"(r3) : "r"(addr))

#define MMA16816(c, a0, a1, a2, a3, b0, b1)                                     \
    asm volatile("mma.sync.aligned.m16n8k16.row.col.f32.f16.f16.f32 "           \
                 "{%0,%1,%2,%3}, {%4,%5,%6,%7}, {%8,%9}, {%0,%1,%2,%3};"        \
                 : "+f"((c)[0]), "+f"((c)[1]), "+f"((c)[2]), "+f"((c)[3])       \
                 : "r"(a0), "r"(a1), "r"(a2), "r"(a3), "r"(b0), "r"(b1))

#define CP_WAIT(n) asm volatile("cp.async.wait_group %0;" ::"n"(n) : "memory")
#define CP_COMMIT() asm volatile("cp.async.commit_group;" ::: "memory")

// ---------------- main GEMM ----------------
__global__ __launch_bounds__(256, 2) void patch_gemm(const float* __restrict__ bias,
                                                     float* __restrict__ out) {
    extern __shared__ char dyn[];
    __shared__ float bias_s[BN];

    const int tid = threadIdx.x;
    const int wid = tid >> 5, lane = tid & 31;
    const int wm = wid & 3;          // 4 warps in M: 32 rows each
    const int wn = wid >> 2;         // 2 warps in N: 64 cols each
    const int nBlock = blockIdx.x * BN;
    const int mBlock = blockIdx.y * BM;

    const uint32_t sbase = (s2u(dyn) + 1023u) & ~1023u;

    if (tid < BN) bias_s[tid] = bias[nBlock + tid];

    // ldmatrix per-lane addressing
    const int lr = (lane & 7) + ((lane >> 3) & 1) * 8;  // row-in-16-block, 0..15
    const int lco = lane >> 4;                          // 0/1: +16B chunk

    float acc[2][8][4];
#pragma unroll
    for (int mi = 0; mi < 2; ++mi)
#pragma unroll
        for (int nj = 0; nj < 8; ++nj)
#pragma unroll
            for (int r = 0; r < 4; ++r) acc[mi][nj][r] = 0.0f;

    // prologue: stages 0,1
    load_stage(sbase + 0 * STAGE_B, 0, mBlock, nBlock, tid);
    CP_COMMIT();
    load_stage(sbase + 1 * STAGE_B, 1, mBlock, nBlock, tid);
    CP_COMMIT();

#pragma unroll 1
    for (int kt = 0; kt < KTILES; ++kt) {
        if (kt + 1 < KTILES) CP_WAIT(1);
        else                 CP_WAIT(0);
        __syncthreads();

        const uint32_t aS = sbase + (kt % NSTAGE) * STAGE_B;
        const uint32_t bS = aS + TILE_B;

        // register double buffers for fragments
        uint32_t a[2][2][4], b[2][4][4];

        // load ks=0 into buffer 0
        {
            const int c0 = lco;
#pragma unroll
            for (int mi = 0; mi < 2; ++mi) {
                int r = wm * 32 + mi * 16 + lr;
                LDSM_X4(a[0][mi][0], a[0][mi][1], a[0][mi][2], a[0][mi][3],
                        aS + sw_off(r, c0));
            }
#pragma unroll
            for (int g = 0; g < 4; ++g) {
                int r = wn * 64 + g * 16 + lr;
                LDSM_X4(b[0][g][0], b[0][g][1], b[0][g][2], b[0][g][3],
                        bS + sw_off(r, c0));
            }
        }

#pragma unroll
        for (int ks = 0; ks < 4; ++ks) {
            const int cur = ks & 1, nxt = cur ^ 1;
            if (ks < 3) {
                const int c1 = 2 * (ks + 1) + lco;
#pragma unroll
                for (int mi = 0; mi < 2; ++mi) {
                    int r = wm * 32 + mi * 16 + lr;
                    LDSM_X4(a[nxt][mi][0], a[nxt][mi][1], a[nxt][mi][2],
                            a[nxt][mi][3], aS + sw_off(r, c1));
                }
#pragma unroll
                for (int g = 0; g < 4; ++g) {
                    int r = wn * 64 + g * 16 + lr;
                    LDSM_X4(b[nxt][g][0], b[nxt][g][1], b[nxt][g][2],
                            b[nxt][g][3], bS + sw_off(r, c1));
                }
            }
#pragma unroll
            for (int mi = 0; mi < 2; ++mi)
#pragma unroll
                for (int g = 0; g < 4; ++g) {
                    MMA16816(acc[mi][2 * g], a[cur][mi][0], a[cur][mi][1],
                             a[cur][mi][2], a[cur][mi][3], b[cur][g][0],
                             b[cur][g][2]);
                    MMA16816(acc[mi][2 * g + 1], a[cur][mi][0], a[cur][mi][1],
                             a[cur][mi][2], a[cur][mi][3], b[cur][g][1],
                             b[cur][g][3]);
                }
        }

        if (kt + 2 < KTILES) {
            load_stage(sbase + ((kt + 2) % NSTAGE) * STAGE_B, kt + 2, mBlock, nBlock,
                       tid);
            CP_COMMIT();
        }
    }

    // ---------------- epilogue: bias + exact GELU, float2 stores ----------------
    const int tig = lane & 3, gid = lane >> 2;
#pragma unroll
    for (int mi = 0; mi < 2; ++mi) {
        const int row0 = mBlock + wm * 32 + mi * 16 + gid;
#pragma unroll
        for (int nj = 0; nj < 8; ++nj) {
            const int cloc = wn * 64 + nj * 8 + tig * 2;
            const float b0 = bias_s[cloc], b1 = bias_s[cloc + 1];
            float2 v0, v1;
            v0.x = gelu_exact(acc[mi][nj][0] + b0);
            v0.y = gelu_exact(acc[mi][nj][1] + b1);
            v1.x = gelu_exact(acc[mi][nj][2] + b0);
            v1.y = gelu_exact(acc[mi][nj][3] + b1);
            *(float2*)(out + (size_t)row0 * N_TOTAL + nBlock + cloc) = v0;
            *(float2*)(out + (size_t)(row0 + 8) * N_TOTAL + nBlock + cloc) = v1;
        }
    }
}

// ---------------- launch ----------------
extern "C" void kernel_launch(void* const* d_in, const int* in_sizes, int n_in,
                              void* d_out, int out_size) {
    const float* img = (const float*)d_in[0];   // [64,224,224,3]
    const float* Wp = (const float*)d_in[1];    // [768,768]
    const float* bias = (const float*)d_in[2];  // [768]
    float* out = (float*)d_out;                 // [64,196,768]

    cudaFuncSetAttribute(patch_gemm, cudaFuncAttributeMaxDynamicSharedMemorySize,
                         SMEM_DYN);

    im2col_prep<<<M_TOTAL * K_TOTAL / 16 / 256, 256>>>(img);
    wprep<<<dim3(N_TOTAL / 32, K_TOTAL / 32), dim3(32, 32)>>>(Wp);
    patch_gemm<<<dim3(N_TOTAL / BN, M_TOTAL / BM), 256, SMEM_DYN>>>(bias, out);
}